// round 13
// baseline (speedup 1.0000x reference)
#include <cuda_runtime.h>

#define B_   4096
#define T_   200
#define S_   20
#define NF_  16
#define NT_  2
#define H1_  128
#define H2_  64
#define H3_  32
#define BT_  16
#define NBLK (B_ / BT_)   // 256
#define NTH  256

// ---- smem layout (float offsets); row stride 20 floats (80B, 16B-aligned) ----
// IN buffer: 144 rows = [x(16 rows); h1(128 rows)], double buffered.
#define ROW   20
#define INB   0
#define IN_SZ 2880                   // 144*20
#define H2B   5760                   // 2 x [64][20] = 2560
#define H2SZ  1280
#define DSO   8320                   // dense: [16][33] = 528
#define SMF   8848
#define SMB   (SMF * 4)              // 35392 B -> 2 CTAs/SM

// ---- prepped weights: [k][u] = float4(gate i,f,g,o) ----
__device__ float4 d_W1v[144 * 128];
__device__ float4 d_W2v[192 * 64];
__device__ float4 d_b1v[128];
__device__ float4 d_b2v[64];

typedef unsigned long long u64;

__device__ __forceinline__ u64 pack2(float lo, float hi) {
    u64 r; asm("mov.b64 %0, {%1, %2};" : "=l"(r) : "f"(lo), "f"(hi)); return r;
}
__device__ __forceinline__ void unpack2(u64 v, float& lo, float& hi) {
    asm("mov.b64 {%0, %1}, %2;" : "=f"(lo), "=f"(hi) : "l"(v));
}
__device__ __forceinline__ u64 fma2(u64 a, u64 b, u64 c) {
    u64 d; asm("fma.rn.f32x2 %0, %1, %2, %3;" : "=l"(d) : "l"(a), "l"(b), "l"(c)); return d;
}
__device__ __forceinline__ float tanhf_(float x) {
    float y; asm("tanh.approx.f32 %0, %1;" : "=f"(y) : "f"(x)); return y;
}
__device__ __forceinline__ float sigmoidf_(float x) {
    return fmaf(0.5f, tanhf_(0.5f * x), 0.5f);
}

// 4 gates x 4 pairs (8 batches), one k
__device__ __forceinline__ void mac4(u64* acc, float4 wv, u64 h0, u64 h1, u64 h2, u64 h3) {
    u64 wi = pack2(wv.x, wv.x), wf = pack2(wv.y, wv.y);
    u64 wg = pack2(wv.z, wv.z), wo = pack2(wv.w, wv.w);
    acc[0]  = fma2(wi, h0, acc[0]);  acc[1]  = fma2(wi, h1, acc[1]);
    acc[2]  = fma2(wi, h2, acc[2]);  acc[3]  = fma2(wi, h3, acc[3]);
    acc[4]  = fma2(wf, h0, acc[4]);  acc[5]  = fma2(wf, h1, acc[5]);
    acc[6]  = fma2(wf, h2, acc[6]);  acc[7]  = fma2(wf, h3, acc[7]);
    acc[8]  = fma2(wg, h0, acc[8]);  acc[9]  = fma2(wg, h1, acc[9]);
    acc[10] = fma2(wg, h2, acc[10]); acc[11] = fma2(wg, h3, acc[11]);
    acc[12] = fma2(wo, h0, acc[12]); acc[13] = fma2(wo, h1, acc[13]);
    acc[14] = fma2(wo, h2, acc[14]); acc[15] = fma2(wo, h3, acc[15]);
}
// 4 gates x 2 pairs (4 batches), one k
__device__ __forceinline__ void mac2(u64* acc, float4 wv, u64 h0, u64 h1) {
    u64 wi = pack2(wv.x, wv.x), wf = pack2(wv.y, wv.y);
    u64 wg = pack2(wv.z, wv.z), wo = pack2(wv.w, wv.w);
    acc[0] = fma2(wi, h0, acc[0]); acc[1] = fma2(wi, h1, acc[1]);
    acc[2] = fma2(wf, h0, acc[2]); acc[3] = fma2(wf, h1, acc[3]);
    acc[4] = fma2(wg, h0, acc[4]); acc[5] = fma2(wg, h1, acc[5]);
    acc[6] = fma2(wo, h0, acc[6]); acc[7] = fma2(wo, h1, acc[7]);
}

__device__ __forceinline__ void acc_init16(u64* acc, float4 bv) {
    u64 bi = pack2(bv.x, bv.x), bf = pack2(bv.y, bv.y);
    u64 bg = pack2(bv.z, bv.z), bo = pack2(bv.w, bv.w);
#pragma unroll
    for (int j = 0; j < 4; j++) { acc[j] = bi; acc[4+j] = bf; acc[8+j] = bg; acc[12+j] = bo; }
}
__device__ __forceinline__ void acc_init8(u64* acc, float4 bv) {
    u64 bi = pack2(bv.x, bv.x), bf = pack2(bv.y, bv.y);
    u64 bg = pack2(bv.z, bv.z), bo = pack2(bv.w, bv.w);
    acc[0] = bi; acc[1] = bi; acc[2] = bf; acc[3] = bf;
    acc[4] = bg; acc[5] = bg; acc[6] = bo; acc[7] = bo;
}

// pointwise: one unit, 8 batches
__device__ __forceinline__ void pw8(const u64* acc, float* cr, float* dst) {
    float hv[8];
#pragma unroll
    for (int j = 0; j < 4; j++) {
        float i0, i1, f0, f1, g0, g1, o0, o1;
        unpack2(acc[j],    i0, i1); unpack2(acc[4+j],  f0, f1);
        unpack2(acc[8+j],  g0, g1); unpack2(acc[12+j], o0, o1);
        float c0 = sigmoidf_(f0) * cr[2*j]   + sigmoidf_(i0) * tanhf_(g0);
        float c1 = sigmoidf_(f1) * cr[2*j+1] + sigmoidf_(i1) * tanhf_(g1);
        cr[2*j] = c0; cr[2*j+1] = c1;
        hv[2*j]   = sigmoidf_(o0) * tanhf_(c0);
        hv[2*j+1] = sigmoidf_(o1) * tanhf_(c1);
    }
    *(float4*)dst       = make_float4(hv[0], hv[1], hv[2], hv[3]);
    *(float4*)(dst + 4) = make_float4(hv[4], hv[5], hv[6], hv[7]);
}
// pointwise: one unit, 4 batches
__device__ __forceinline__ void pw4(const u64* acc, float* cr, float* dst) {
    float hv[4];
#pragma unroll
    for (int j = 0; j < 2; j++) {
        float i0, i1, f0, f1, g0, g1, o0, o1;
        unpack2(acc[j],   i0, i1); unpack2(acc[2+j], f0, f1);
        unpack2(acc[4+j], g0, g1); unpack2(acc[6+j], o0, o1);
        float c0 = sigmoidf_(f0) * cr[2*j]   + sigmoidf_(i0) * tanhf_(g0);
        float c1 = sigmoidf_(f1) * cr[2*j+1] + sigmoidf_(i1) * tanhf_(g1);
        cr[2*j] = c0; cr[2*j+1] = c1;
        hv[2*j]   = sigmoidf_(o0) * tanhf_(c0);
        hv[2*j+1] = sigmoidf_(o1) * tanhf_(c1);
    }
    *(float4*)dst = make_float4(hv[0], hv[1], hv[2], hv[3]);
}

// ---- layer 1: thread = unit u (tid&127) x batches 8*bg.. (bg=tid>>7) ----
// Unified 144-row input [x; h1], register double-buffered weight prefetch.
__device__ __forceinline__ void layer1(float* sm, int u, int bg, int p, float* c1r) {
    u64 acc[16];
    acc_init16(acc, d_b1v[u]);
    const float4* __restrict__ w = d_W1v + u;
    const float* in = sm + INB + p * IN_SZ + 8 * bg;

    float4 wb0 = w[0], wb1 = w[128], wb2 = w[256], wb3 = w[384];
#pragma unroll 1
    for (int kb = 0; kb < 140; kb += 4) {
        float4 wc0 = wb0, wc1 = wb1, wc2 = wb2, wc3 = wb3;
        const float4* wn = w + (kb + 4) * 128;
        wb0 = wn[0]; wb1 = wn[128]; wb2 = wn[256]; wb3 = wn[384];
        const ulonglong2* r0 = (const ulonglong2*)(in + kb * ROW);
        const ulonglong2* r1 = (const ulonglong2*)(in + (kb + 1) * ROW);
        const ulonglong2* r2 = (const ulonglong2*)(in + (kb + 2) * ROW);
        const ulonglong2* r3 = (const ulonglong2*)(in + (kb + 3) * ROW);
        ulonglong2 a0 = r0[0], b0 = r0[1];
        ulonglong2 a1 = r1[0], b1 = r1[1];
        ulonglong2 a2 = r2[0], b2 = r2[1];
        ulonglong2 a3 = r3[0], b3 = r3[1];
        mac4(acc, wc0, a0.x, a0.y, b0.x, b0.y);
        mac4(acc, wc1, a1.x, a1.y, b1.x, b1.y);
        mac4(acc, wc2, a2.x, a2.y, b2.x, b2.y);
        mac4(acc, wc3, a3.x, a3.y, b3.x, b3.y);
    }
    {   // epilogue k = 140..143
        const ulonglong2* r0 = (const ulonglong2*)(in + 140 * ROW);
        const ulonglong2* r1 = (const ulonglong2*)(in + 141 * ROW);
        const ulonglong2* r2 = (const ulonglong2*)(in + 142 * ROW);
        const ulonglong2* r3 = (const ulonglong2*)(in + 143 * ROW);
        ulonglong2 a0 = r0[0], b0 = r0[1];
        ulonglong2 a1 = r1[0], b1 = r1[1];
        ulonglong2 a2 = r2[0], b2 = r2[1];
        ulonglong2 a3 = r3[0], b3 = r3[1];
        mac4(acc, wb0, a0.x, a0.y, b0.x, b0.y);
        mac4(acc, wb1, a1.x, a1.y, b1.x, b1.y);
        mac4(acc, wb2, a2.x, a2.y, b2.x, b2.y);
        mac4(acc, wb3, a3.x, a3.y, b3.x, b3.y);
    }
    pw8(acc, c1r, sm + INB + (p ^ 1) * IN_SZ + (16 + u) * ROW + 8 * bg);
}

// ---- layer 2: thread = unit u2 (tid&63) x batches 4*q.. (q=tid>>6) ----
__device__ __forceinline__ void layer2(float* sm, int u2, int q, int p, float* c2r) {
    u64 acc[8];
    acc_init8(acc, d_b2v[u2]);
    const float4* __restrict__ w = d_W2v + u2;
    const float* h1n = sm + INB + (p ^ 1) * IN_SZ + 16 * ROW + 4 * q;
    const float* h2r = sm + H2B + p * H2SZ + 4 * q;

    float4 wb0 = w[0], wb1 = w[64], wb2 = w[128], wb3 = w[192];
#pragma unroll 1
    for (int kb = 0; kb < 124; kb += 4) {
        float4 wc0 = wb0, wc1 = wb1, wc2 = wb2, wc3 = wb3;
        const float4* wn = w + (kb + 4) * 64;
        wb0 = wn[0]; wb1 = wn[64]; wb2 = wn[128]; wb3 = wn[192];
        ulonglong2 a0 = *(const ulonglong2*)(h1n + kb * ROW);
        ulonglong2 a1 = *(const ulonglong2*)(h1n + (kb + 1) * ROW);
        ulonglong2 a2 = *(const ulonglong2*)(h1n + (kb + 2) * ROW);
        ulonglong2 a3 = *(const ulonglong2*)(h1n + (kb + 3) * ROW);
        mac2(acc, wc0, a0.x, a0.y);
        mac2(acc, wc1, a1.x, a1.y);
        mac2(acc, wc2, a2.x, a2.y);
        mac2(acc, wc3, a3.x, a3.y);
    }
    {   // bridge block k=124..127, prefetch seg2 start (k=128..131)
        float4 wc0 = wb0, wc1 = wb1, wc2 = wb2, wc3 = wb3;
        const float4* wn = w + 128 * 64;
        wb0 = wn[0]; wb1 = wn[64]; wb2 = wn[128]; wb3 = wn[192];
        ulonglong2 a0 = *(const ulonglong2*)(h1n + 124 * ROW);
        ulonglong2 a1 = *(const ulonglong2*)(h1n + 125 * ROW);
        ulonglong2 a2 = *(const ulonglong2*)(h1n + 126 * ROW);
        ulonglong2 a3 = *(const ulonglong2*)(h1n + 127 * ROW);
        mac2(acc, wc0, a0.x, a0.y);
        mac2(acc, wc1, a1.x, a1.y);
        mac2(acc, wc2, a2.x, a2.y);
        mac2(acc, wc3, a3.x, a3.y);
    }
#pragma unroll 1
    for (int kb = 0; kb < 60; kb += 4) {
        float4 wc0 = wb0, wc1 = wb1, wc2 = wb2, wc3 = wb3;
        const float4* wn = w + (128 + kb + 4) * 64;
        wb0 = wn[0]; wb1 = wn[64]; wb2 = wn[128]; wb3 = wn[192];
        ulonglong2 a0 = *(const ulonglong2*)(h2r + kb * ROW);
        ulonglong2 a1 = *(const ulonglong2*)(h2r + (kb + 1) * ROW);
        ulonglong2 a2 = *(const ulonglong2*)(h2r + (kb + 2) * ROW);
        ulonglong2 a3 = *(const ulonglong2*)(h2r + (kb + 3) * ROW);
        mac2(acc, wc0, a0.x, a0.y);
        mac2(acc, wc1, a1.x, a1.y);
        mac2(acc, wc2, a2.x, a2.y);
        mac2(acc, wc3, a3.x, a3.y);
    }
    {   // epilogue k=188..191 (local 60..63)
        ulonglong2 a0 = *(const ulonglong2*)(h2r + 60 * ROW);
        ulonglong2 a1 = *(const ulonglong2*)(h2r + 61 * ROW);
        ulonglong2 a2 = *(const ulonglong2*)(h2r + 62 * ROW);
        ulonglong2 a3 = *(const ulonglong2*)(h2r + 63 * ROW);
        mac2(acc, wb0, a0.x, a0.y);
        mac2(acc, wb1, a1.x, a1.y);
        mac2(acc, wb2, a2.x, a2.y);
        mac2(acc, wb3, a3.x, a3.y);
    }
    pw4(acc, c2r, sm + H2B + (p ^ 1) * H2SZ + u2 * ROW + 4 * q);
}

// ---- weight prep ----
__global__ void prep_kernel(const float* __restrict__ Wih1, const float* __restrict__ Whh1,
                            const float* __restrict__ bih1, const float* __restrict__ bhh1,
                            const float* __restrict__ Wih2, const float* __restrict__ Whh2,
                            const float* __restrict__ bih2, const float* __restrict__ bhh2) {
    int idx = blockIdx.x * blockDim.x + threadIdx.x;
    int stride = gridDim.x * blockDim.x;
    for (int i = idx; i < 144*128; i += stride) {
        int k = i >> 7, u = i & 127;
        float4 v;
        if (k < NF_) {
            v = make_float4(Wih1[u*NF_ + k], Wih1[(H1_+u)*NF_ + k],
                            Wih1[(2*H1_+u)*NF_ + k], Wih1[(3*H1_+u)*NF_ + k]);
        } else {
            int kk = k - NF_;
            v = make_float4(Whh1[u*H1_ + kk], Whh1[(H1_+u)*H1_ + kk],
                            Whh1[(2*H1_+u)*H1_ + kk], Whh1[(3*H1_+u)*H1_ + kk]);
        }
        d_W1v[i] = v;
    }
    for (int i = idx; i < 192*64; i += stride) {
        int k = i >> 6, u = i & 63;
        float4 v;
        if (k < H1_) {
            v = make_float4(Wih2[u*H1_ + k], Wih2[(H2_+u)*H1_ + k],
                            Wih2[(2*H2_+u)*H1_ + k], Wih2[(3*H2_+u)*H1_ + k]);
        } else {
            int kk = k - H1_;
            v = make_float4(Whh2[u*H2_ + kk], Whh2[(H2_+u)*H2_ + kk],
                            Whh2[(2*H2_+u)*H2_ + kk], Whh2[(3*H2_+u)*H2_ + kk]);
        }
        d_W2v[i] = v;
    }
    if (idx < H1_)
        d_b1v[idx] = make_float4(bih1[idx] + bhh1[idx], bih1[H1_+idx] + bhh1[H1_+idx],
                                 bih1[2*H1_+idx] + bhh1[2*H1_+idx], bih1[3*H1_+idx] + bhh1[3*H1_+idx]);
    if (idx < H2_)
        d_b2v[idx] = make_float4(bih2[idx] + bhh2[idx], bih2[H2_+idx] + bhh2[H2_+idx],
                                 bih2[2*H2_+idx] + bhh2[2*H2_+idx], bih2[3*H2_+idx] + bhh2[3*H2_+idx]);
}

// ---- main persistent kernel: 2 CTAs per SM ----
__global__ void __launch_bounds__(NTH, 2) lstm_main(
    const float* __restrict__ xh, const float* __restrict__ xfut,
    const float* __restrict__ Wd, const float* __restrict__ bd,
    const float* __restrict__ Wf, const float* __restrict__ bf,
    const float* __restrict__ ob, float* __restrict__ out) {
    extern __shared__ float sm[];
    const int tid = threadIdx.x;
    const int b0  = blockIdx.x * BT_;
    const int u  = tid & 127, bg = tid >> 7;
    const int u2 = tid & 63,  q  = tid >> 6;

    for (int i = tid; i < SMF; i += NTH) sm[i] = 0.0f;

    float c1r[8], c2r[4];
#pragma unroll
    for (int j = 0; j < 8; j++) c1r[j] = 0.0f;
#pragma unroll
    for (int j = 0; j < 4; j++) c2r[j] = 0.0f;

    // load x_0 into IN[0] rows 0..15
    {
        int f = tid >> 4, bt = tid & 15;
        sm[INB + f*ROW + bt] = xh[(size_t)(b0 + bt) * T_ * NF_ + f];
    }
    __syncthreads();

    int p = 0;
    // ---------- encoder ----------
    for (int t = 0; t < T_; t++) {
        layer1(sm, u, bg, p, c1r);
        __syncthreads();
        layer2(sm, u2, q, p, c2r);
        if (t < T_ - 1) {
            int f = tid >> 4, bt = tid & 15;
            sm[INB + (p^1)*IN_SZ + f*ROW + bt] =
                xh[(size_t)(b0 + bt) * T_ * NF_ + (size_t)(t+1)*NF_ + f];
        }
        __syncthreads();
        p ^= 1;
    }
    // p == 0 here. IN[0] holds h1(199); h2[0] holds h2(199).

    // decoder prep: refs(0) -> IN[0] rows 0..13; cur = x(199)[14:16] from IN[1]
    if (tid < 14 * BT_) {
        int f = tid % 14, bt = tid / 14;
        sm[INB + f*ROW + bt] = xfut[(size_t)(b0 + bt) * S_ * 14 + f];
    } else {
        int cc = tid - 224;           // 0..31
        int bt = cc >> 1, tt = cc & 1;
        sm[INB + (14 + tt)*ROW + bt] = sm[INB + IN_SZ + (14 + tt)*ROW + bt];
    }
    __syncthreads();

    // ---------- decoder ----------
    for (int st = 0; st < S_; st++) {
        layer1(sm, u, bg, p, c1r);
        __syncthreads();
        layer2(sm, u2, q, p, c2r);
        if (st < S_ - 1 && tid < 14 * BT_) {
            int f = tid % 14, bt = tid / 14;
            sm[INB + (p^1)*IN_SZ + f*ROW + bt] =
                xfut[(size_t)(b0 + bt) * S_ * 14 + (size_t)(st+1)*14 + f];
        }
        __syncthreads();

        // dense: DS[bt][du] = relu(h2_new @ Wd^T + bd)
        {
            int du = tid & 31, qq = tid >> 5;
            const float* h2n = sm + H2B + (p^1)*H2SZ;
            float a0 = 0.f, a1 = 0.f;
#pragma unroll 4
            for (int k = 0; k < H2_; k++) {
                float wv = Wd[du*H2_ + k];
                const float* r = h2n + k*ROW;
                a0 = fmaf(wv, r[qq],     a0);
                a1 = fmaf(wv, r[qq + 8], a1);
            }
            float bdv = bd[du];
            sm[DSO + qq*33 + du]     = fmaxf(a0 + bdv, 0.f);
            sm[DSO + (qq+8)*33 + du] = fmaxf(a1 + bdv, 0.f);
        }
        __syncthreads();

        // pred + feedback into IN[p^1] rows 14,15
        if (tid < BT_ * NT_) {
            int bt = tid >> 1, tt = tid & 1;
            float acc = 0.f;
#pragma unroll
            for (int k = 0; k < H3_; k++)
                acc = fmaf(sm[DSO + bt*33 + k], Wf[tt*H3_ + k], acc);
            float pr = acc + bf[tt] + ob[tt];
            out[(size_t)(b0 + bt) * S_ * NT_ + st * NT_ + tt] = pr;
            sm[INB + (p^1)*IN_SZ + (14 + tt)*ROW + bt] = pr;
        }
        __syncthreads();
        p ^= 1;
    }
}

// ---- launch ----
extern "C" void kernel_launch(void* const* d_in, const int* in_sizes, int n_in,
                              void* d_out, int out_size) {
    (void)in_sizes; (void)n_in; (void)out_size;
    const float* xh   = (const float*)d_in[0];
    const float* xfut = (const float*)d_in[1];
    const float* Wih1 = (const float*)d_in[2];
    const float* Whh1 = (const float*)d_in[3];
    const float* bih1 = (const float*)d_in[4];
    const float* bhh1 = (const float*)d_in[5];
    const float* Wih2 = (const float*)d_in[6];
    const float* Whh2 = (const float*)d_in[7];
    const float* bih2 = (const float*)d_in[8];
    const float* bhh2 = (const float*)d_in[9];
    const float* Wd   = (const float*)d_in[10];
    const float* bd   = (const float*)d_in[11];
    const float* Wf   = (const float*)d_in[12];
    const float* bf   = (const float*)d_in[13];
    const float* ob   = (const float*)d_in[14];
    float* out = (float*)d_out;

    cudaFuncSetAttribute(lstm_main, cudaFuncAttributeMaxDynamicSharedMemorySize, SMB);
    prep_kernel<<<128, 256>>>(Wih1, Whh1, bih1, bhh1, Wih2, Whh2, bih2, bhh2);
    lstm_main<<<NBLK, NTH, SMB>>>(xh, xfut, Wd, bd, Wf, bf, ob, out);
}

// round 15
// speedup vs baseline: 2.4646x; 2.4646x over previous
#include <cuda_runtime.h>
#include <cuda_bf16.h>
#include <cstdint>

typedef unsigned int u32;

#define T_ 200
#define S_ 20
#define KS1 27              // K1=432 = 3*144, 16 per step
#define KS2 36              // K2=576 = 3*192
#define KP1 456             // B1 row stride (elems): 912B, conflict-free
#define KP2 584             // B2 row stride: 1168B

#define O_B1 0
#define SZ_B1 (32*KP1*2)
#define O_B2 (O_B1+SZ_B1)
#define SZ_B2 (32*KP2*2)
#define O_H2F (O_B2+SZ_B2)
#define O_DS  (O_H2F+64*33*4)
#define SMEMB (O_DS+32*33*4)

__device__ __align__(16) unsigned char dA1[KS1*8*4*512];   // 442368 B
__device__ __align__(16) unsigned char dA2[KS2*8*2*512];   // 294912 B
__device__ float dBi1[512];
__device__ float dBi2[256];

__device__ __forceinline__ float th_(float x){float y;asm("tanh.approx.f32 %0,%1;":"=f"(y):"f"(x));return y;}
__device__ __forceinline__ float sg_(float x){return fmaf(0.5f,th_(0.5f*x),0.5f);}

__device__ __forceinline__ void mma_(float* d,const uint4 a,u32 b0,u32 b1){
    asm volatile("mma.sync.aligned.m16n8k16.row.col.f32.bf16.bf16.f32 "
        "{%0,%1,%2,%3},{%4,%5,%6,%7},{%8,%9},{%0,%1,%2,%3};"
        :"+f"(d[0]),"+f"(d[1]),"+f"(d[2]),"+f"(d[3])
        :"r"(a.x),"r"(a.y),"r"(a.z),"r"(a.w),"r"(b0),"r"(b1));
}
// write value v as 3-term bf16 (hi,lo,hi) at columns 3k..3k+2 of batch-row n
__device__ __forceinline__ void put3(unsigned char* B,int kpad,int n,int k3,float v){
    __nv_bfloat16 h=__float2bfloat16(v);
    __nv_bfloat16 l=__float2bfloat16(v-__bfloat162float(h));
    __nv_bfloat16* p=(__nv_bfloat16*)(B+(size_t)n*kpad*2)+k3;
    p[0]=h; p[1]=l; p[2]=h;
}
__device__ __forceinline__ void loadA1(uint4* d,int ks,int wid,int lane){
    const uint4* p=(const uint4*)dA1+(size_t)((ks*8+wid)*4)*32+lane;
#pragma unroll
    for(int mt=0;mt<4;mt++) d[mt]=p[mt*32];
}
__device__ __forceinline__ void loadA2(uint4* d,int ks,int wid,int lane){
    const uint4* p=(const uint4*)dA2+(size_t)((ks*8+wid)*2)*32+lane;
    d[0]=p[0]; d[1]=p[32];
}
__device__ __forceinline__ void bfrag(const unsigned char* Bb,int kpad,int ks,int gq,int t,u32* b0,u32* b1){
#pragma unroll
    for(int nt=0;nt<4;nt++){
        const unsigned char* p=Bb+((size_t)(nt*8+gq)*kpad+ks*16+2*t)*2;
        b0[nt]=*(const u32*)p; b1[nt]=*(const u32*)(p+16);
    }
}

// ---- prep: pack weights into HMMA A-fragment order, 3-term interleaved ----
__global__ void prep(const float* Wih1,const float* Whh1,const float* bih1,const float* bhh1,
                     const float* Wih2,const float* Whh2,const float* bih2,const float* bhh2){
    int idx=blockIdx.x*blockDim.x+threadIdx.x, st=gridDim.x*blockDim.x;
    for(int e=idx;e<KS1*8*4*256;e+=st){
        int blk=e>>3,sub=e&7,reg=sub>>1,half=sub&1;
        int lane=blk&31,mt=(blk>>5)&3,w=(blk>>7)&7,ks=blk>>10;
        int gq=lane>>2,t=lane&3;
        int lrow=gq+((reg&1)<<3), lcol=2*t+((reg>>1)<<3)+half;
        int gate=mt, unit=w*16+lrow;
        int kp=ks*16+lcol, term=kp%3, kk=kp/3;
        float wv=(kk<16)?Wih1[(gate*128+unit)*16+kk]:Whh1[(gate*128+unit)*128+kk-16];
        float hi=__bfloat162float(__float2bfloat16(wv));
        float v=(term<2)?hi:(wv-hi);
        ((__nv_bfloat16*)dA1)[blk*8+sub]=__float2bfloat16(v);
    }
    for(int e=idx;e<KS2*8*2*256;e+=st){
        int blk=e>>3,sub=e&7,reg=sub>>1,half=sub&1;
        int lane=blk&31,mt=(blk>>5)&1,w=(blk>>6)&7,ks=blk>>9;
        int gq=lane>>2,t=lane&3;
        int lrow=gq+((reg&1)<<3), lcol=2*t+((reg>>1)<<3)+half;
        int rr=mt*16+lrow, gate=rr>>3, unit=w*8+(rr&7);
        int kp=ks*16+lcol, term=kp%3, kk=kp/3;
        float wv=(kk<128)?Wih2[(gate*64+unit)*128+kk]:Whh2[(gate*64+unit)*64+kk-128];
        float hi=__bfloat162float(__float2bfloat16(wv));
        float v=(term<2)?hi:(wv-hi);
        ((__nv_bfloat16*)dA2)[blk*8+sub]=__float2bfloat16(v);
    }
    for(int i=idx;i<512;i+=st) dBi1[i]=bih1[i]+bhh1[i];
    for(int i=idx;i<256;i+=st) dBi2[i]=bih2[i]+bhh2[i];
}

// ---- main persistent HMMA kernel ----
__global__ void __launch_bounds__(256,1) lstm_tc(
    const float* __restrict__ xh,const float* __restrict__ xf,
    const float* __restrict__ Wd,const float* __restrict__ bd,
    const float* __restrict__ Wf,const float* __restrict__ bfv,
    const float* __restrict__ ob,float* __restrict__ out){
    extern __shared__ unsigned char sm[];
    const int tid=threadIdx.x, wid=tid>>5, lane=tid&31;
    const int gq=lane>>2, t=lane&3;
    const int b0=blockIdx.x*32;

    for(int i=tid*16;i<SMEMB;i+=256*16) *(uint4*)(sm+i)=make_uint4(0,0,0,0);

    // per-thread biases (constant across steps)
    float bi1[2][4], bi2[4];
#pragma unroll
    for(int us=0;us<2;us++)
#pragma unroll
        for(int gt=0;gt<4;gt++) bi1[us][gt]=dBi1[gt*128+wid*16+gq+us*8];
#pragma unroll
    for(int gt=0;gt<4;gt++) bi2[gt]=dBi2[gt*64+wid*8+gq];

    float c1r[16], c2r[8];
#pragma unroll
    for(int j=0;j<16;j++) c1r[j]=0.f;
#pragma unroll
    for(int j=0;j<8;j++) c2r[j]=0.f;
    __syncthreads();

    for(int ts=0;ts<T_+S_;ts++){
        const int dec=ts>=T_; const int tt0=dec?ts-T_:ts;
        // input -> B1 (x cols 3f..; decoder: refs cols, cur persists at 3*14..)
        if(!dec){
#pragma unroll
            for(int r=0;r<2;r++){
                int i2=tid*2+r, bt=i2>>4, f=i2&15;
                put3(sm+O_B1,KP1,bt,3*f, xh[(size_t)(b0+bt)*T_*16+(size_t)tt0*16+f]);
            }
        } else if(tid<224){
#pragma unroll
            for(int r=0;r<2;r++){
                int i2=tid*2+r, f=i2%14, bt=i2/14;
                put3(sm+O_B1,KP1,bt,3*f, xf[(size_t)(b0+bt)*S_*14+(size_t)tt0*14+f]);
            }
        }
        __syncthreads();

        // ---- layer 1: M=512, 27 k-steps ----
        float ac[4][16];
#pragma unroll
        for(int m=0;m<4;m++)
#pragma unroll
            for(int j2=0;j2<16;j2++) ac[m][j2]=0.f;
        {
            uint4 A[4],N[4];
            loadA1(A,0,wid,lane); loadA1(N,1,wid,lane);
            u32 b0f[4],b1f[4];
#pragma unroll 1
            for(int ks=0;ks<26;ks+=2){
                bfrag(sm+O_B1,KP1,ks,gq,t,b0f,b1f);
#pragma unroll
                for(int mt=0;mt<4;mt++)
#pragma unroll
                    for(int nt=0;nt<4;nt++) mma_(&ac[mt][nt*4],A[mt],b0f[nt],b1f[nt]);
                if(ks+2<KS1) loadA1(A,ks+2,wid,lane);
                bfrag(sm+O_B1,KP1,ks+1,gq,t,b0f,b1f);
#pragma unroll
                for(int mt=0;mt<4;mt++)
#pragma unroll
                    for(int nt=0;nt<4;nt++) mma_(&ac[mt][nt*4],N[mt],b0f[nt],b1f[nt]);
                if(ks+3<KS1) loadA1(N,ks+3,wid,lane);
            }
            bfrag(sm+O_B1,KP1,26,gq,t,b0f,b1f);   // tail ks=26 (in A)
#pragma unroll
            for(int mt=0;mt<4;mt++)
#pragma unroll
                for(int nt=0;nt<4;nt++) mma_(&ac[mt][nt*4],A[mt],b0f[nt],b1f[nt]);
        }
        __syncthreads();
        // epilogue 1 (in-register pointwise)
#pragma unroll
        for(int us=0;us<2;us++)
#pragma unroll
            for(int nt=0;nt<4;nt++)
#pragma unroll
                for(int j=0;j<2;j++){
                    int ci=us*8+nt*2+j;
                    float gi=ac[0][nt*4+us*2+j]+bi1[us][0];
                    float gf=ac[1][nt*4+us*2+j]+bi1[us][1];
                    float gg=ac[2][nt*4+us*2+j]+bi1[us][2];
                    float go=ac[3][nt*4+us*2+j]+bi1[us][3];
                    float c=sg_(gf)*c1r[ci]+sg_(gi)*th_(gg); c1r[ci]=c;
                    float h=sg_(go)*th_(c);
                    int unit=wid*16+gq+us*8, n=nt*8+2*t+j;
                    put3(sm+O_B1,KP1,n,3*(16+unit),h);
                    put3(sm+O_B2,KP2,n,3*unit,h);
                }
        __syncthreads();

        // ---- layer 2: M=256, 36 k-steps ----
        float ac2[2][16];
#pragma unroll
        for(int m=0;m<2;m++)
#pragma unroll
            for(int j2=0;j2<16;j2++) ac2[m][j2]=0.f;
        {
            uint4 A[2],N[2];
            loadA2(A,0,wid,lane); loadA2(N,1,wid,lane);
            u32 b0f[4],b1f[4];
#pragma unroll 1
            for(int ks=0;ks<KS2;ks+=2){
                bfrag(sm+O_B2,KP2,ks,gq,t,b0f,b1f);
#pragma unroll
                for(int mt=0;mt<2;mt++)
#pragma unroll
                    for(int nt=0;nt<4;nt++) mma_(&ac2[mt][nt*4],A[mt],b0f[nt],b1f[nt]);
                if(ks+2<KS2) loadA2(A,ks+2,wid,lane);
                bfrag(sm+O_B2,KP2,ks+1,gq,t,b0f,b1f);
#pragma unroll
                for(int mt=0;mt<2;mt++)
#pragma unroll
                    for(int nt=0;nt<4;nt++) mma_(&ac2[mt][nt*4],N[mt],b0f[nt],b1f[nt]);
                if(ks+3<KS2) loadA2(N,ks+3,wid,lane);
            }
        }
        __syncthreads();
        // epilogue 2: thread = unit u2=wid*8+gq, 8 batches
#pragma unroll
        for(int nt=0;nt<4;nt++)
#pragma unroll
            for(int j=0;j<2;j++){
                int ci=nt*2+j;
                float gi=ac2[0][nt*4+j]  +bi2[0];
                float gf=ac2[0][nt*4+2+j]+bi2[1];
                float gg=ac2[1][nt*4+j]  +bi2[2];
                float go=ac2[1][nt*4+2+j]+bi2[3];
                float c=sg_(gf)*c2r[ci]+sg_(gi)*th_(gg); c2r[ci]=c;
                float h=sg_(go)*th_(c);
                int u2=wid*8+gq, n=nt*8+2*t+j;
                put3(sm+O_B2,KP2,n,3*(128+u2),h);
                if(dec) ((float*)(sm+O_H2F))[u2*33+n]=h;
            }
        __syncthreads();

        if(dec){
            // dense 32x64 + relu
            {
                int du=tid&31, g8=tid>>5;
                const float* h2f=(const float*)(sm+O_H2F);
                float a0=0.f,a1=0.f,a2=0.f,a3=0.f;
#pragma unroll 4
                for(int k=0;k<64;k++){
                    float w=Wd[du*64+k];
                    const float* r=h2f+k*33+g8*4;
                    a0=fmaf(w,r[0],a0); a1=fmaf(w,r[1],a1);
                    a2=fmaf(w,r[2],a2); a3=fmaf(w,r[3],a3);
                }
                float bdv=bd[du];
                float* ds=(float*)(sm+O_DS);
                ds[(g8*4+0)*33+du]=fmaxf(a0+bdv,0.f);
                ds[(g8*4+1)*33+du]=fmaxf(a1+bdv,0.f);
                ds[(g8*4+2)*33+du]=fmaxf(a2+bdv,0.f);
                ds[(g8*4+3)*33+du]=fmaxf(a3+bdv,0.f);
            }
            __syncthreads();
            if(tid<64){
                int bt=tid>>1, t2=tid&1;
                const float* ds=(const float*)(sm+O_DS);
                float acc=0.f;
#pragma unroll
                for(int k=0;k<32;k++) acc=fmaf(ds[bt*33+k],Wf[t2*32+k],acc);
                float pr=acc+bfv[t2]+ob[t2];
                out[(size_t)(b0+bt)*S_*2+(size_t)tt0*2+t2]=pr;
                put3(sm+O_B1,KP1,bt,3*(14+t2),pr);   // feedback cur
            }
            __syncthreads();
        }
    }
}

extern "C" void kernel_launch(void* const* d_in, const int* in_sizes, int n_in,
                              void* d_out, int out_size){
    (void)in_sizes;(void)n_in;(void)out_size;
    prep<<<64,256>>>((const float*)d_in[2],(const float*)d_in[3],
                     (const float*)d_in[4],(const float*)d_in[5],
                     (const float*)d_in[6],(const float*)d_in[7],
                     (const float*)d_in[8],(const float*)d_in[9]);
    cudaFuncSetAttribute(lstm_tc,cudaFuncAttributeMaxDynamicSharedMemorySize,SMEMB);
    lstm_tc<<<128,256,SMEMB>>>((const float*)d_in[0],(const float*)d_in[1],
                               (const float*)d_in[10],(const float*)d_in[11],
                               (const float*)d_in[12],(const float*)d_in[13],
                               (const float*)d_in[14],(float*)d_out);
}